// round 9
// baseline (speedup 1.0000x reference)
#include <cuda_runtime.h>
#include <cstdint>

#define N_NODES 100000
#define D 128
#define N_EDGES 1000000
#define M_TILE 128
#define NUM_TILES ((N_NODES + M_TILE - 1) / M_TILE)   // 782

// Scratch (no allocation allowed -> __device__ globals)
__device__ alignas(16) float g_aggA[(size_t)N_NODES * D];
__device__ alignas(16) float g_aggB[(size_t)N_NODES * D];
__device__ alignas(16) float g_h1 [(size_t)N_NODES * D];
__device__ alignas(16) float g_p  [(size_t)N_NODES * D];   // x@Wr partial
__device__ alignas(16) float g_cnt[N_NODES];

// ---------------------------------------------------------------------------
// Zero a float buffer
// ---------------------------------------------------------------------------
__global__ void zero_kernel(float4* p, int count4) {
    int i = blockIdx.x * blockDim.x + threadIdx.x;
    int stride = gridDim.x * blockDim.x;
    float4 z = make_float4(0.f, 0.f, 0.f, 0.f);
    for (; i < count4; i += stride) p[i] = z;
}

// ---------------------------------------------------------------------------
// Scatter: one warp per edge; lane l handles float4 l of the 128-float row.
// Vector reduction (red.global.add.v4.f32). do_count: lane 0 bumps degree.
// ---------------------------------------------------------------------------
__global__ void scatter_kernel(const int* __restrict__ ei,
                               const float* __restrict__ x,
                               float* __restrict__ agg,
                               int do_count) {
    int gt = blockIdx.x * blockDim.x + threadIdx.x;
    int lane = gt & 31;
    int warp = gt >> 5;
    int nwarps = (gridDim.x * blockDim.x) >> 5;
    for (int e = warp; e < N_EDGES; e += nwarps) {
        int s = ei[e];
        int d = ei[N_EDGES + e];
        s = min(max(s, 0), N_NODES - 1);
        d = min(max(d, 0), N_NODES - 1);
        if (do_count && lane == 0) atomicAdd(&g_cnt[d], 1.0f);
        const float4* srcp = (const float4*)(x + (size_t)s * D);
        float4 v = srcp[lane];
        float* dst = agg + (size_t)d * D + lane * 4;
        asm volatile("red.global.add.v4.f32 [%0], {%1,%2,%3,%4};"
                     :: "l"(dst), "f"(v.x), "f"(v.y), "f"(v.z), "f"(v.w)
                     : "memory");
    }
}

// ---------------------------------------------------------------------------
// Half-GEMM (K=128) via mma.sync tf32 m16n8k8, software-pipelined.
//   AGG=false: out[m,:] = a_src[m,:] @ W          (partial, no bias)
//   AGG=true : out[m,:] = act( (a_src[m,:]/cnt[m]) @ W + p_in[m,:] + bias )
// B = W^T staged once per block; A double-buffered, register-prefetched,
// ONE __syncthreads per chunk (2 chunks of 64 k).
//   wB[ka][n][kk]: word = ka*1024 + n*8 + kk      (CF per half-warp)
//   aS[m][kq*4]  : word = m*72 + kq*4             (stride 72 ≡ 8 mod 32, CF)
// ---------------------------------------------------------------------------
#define BH_WORDS (16 * 1024)             // 16 katoms * 128 n * 8 kk
#define A_STRIDE 72
#define A_WORDS (128 * A_STRIDE)         // 9216
#define GEMM_SMEM_BYTES ((BH_WORDS + 2 * A_WORDS) * 4)   // 139264

__device__ __forceinline__ uint32_t f2tf32(float v) {
    uint32_t r;
    asm("cvt.rna.tf32.f32 %0, %1;" : "=r"(r) : "f"(v));
    return r;
}

template <bool AGG>
__global__ void __launch_bounds__(512, 1)
gemm_half(const float* __restrict__ a_src,
          const float* __restrict__ w,      // [128][128] row-major (k, n)
          const float* __restrict__ bias,   // AGG only
          const float* __restrict__ p_in,   // AGG only
          float* __restrict__ out,
          int do_relu) {
    extern __shared__ float sm[];
    float* wB = sm;               // [16 ka][128 n][8 kk]
    float* aS0 = sm + BH_WORDS;
    float* aS1 = aS0 + A_WORDS;

    const int tid = threadIdx.x;
    const int wid = tid >> 5;
    const int lane = tid & 31;
    const int grp = lane >> 2;
    const int tig = lane & 3;
    const int warp_m = wid & 3;
    const int warp_n = wid >> 2;

    int sm_m[4], sm_kq[4];
#pragma unroll
    for (int q = 0; q < 4; q++) {
        int i = tid + q * 512;
        sm_m[q] = i >> 4;
        sm_kq[q] = i & 15;
    }

    // ---- Stage B = W^T once: wB[ka][n][kk] = tf32(W[ka*8+kk][n]) ----
    for (int i = tid; i < 4096; i += 512) {
        int n = i & 127;
        int t2 = i >> 7;          // 0..31
        int ka = t2 >> 1;
        int h = t2 & 1;
        int kb = ka * 8 + h * 4;
        float4 c;
        c.x = __uint_as_float(f2tf32(w[(kb + 0) * 128 + n]));
        c.y = __uint_as_float(f2tf32(w[(kb + 1) * 128 + n]));
        c.z = __uint_as_float(f2tf32(w[(kb + 2) * 128 + n]));
        c.w = __uint_as_float(f2tf32(w[(kb + 3) * 128 + n]));
        *(float4*)&wB[ka * 1024 + n * 8 + h * 4] = c;
    }

    float4 rv[4];
    float cf[4];

    auto load_chunk = [&](int m_base, int chunk) {
#pragma unroll
        for (int q = 0; q < 4; q++) {
            int gm = m_base + sm_m[q];
            rv[q] = make_float4(0.f, 0.f, 0.f, 0.f);
            if (AGG) cf[q] = 1.f;
            if (gm < N_NODES) {
                int kg = chunk * 64 + (sm_kq[q] << 2);
                rv[q] = *(const float4*)(a_src + (size_t)gm * D + kg);
                if (AGG) cf[q] = g_cnt[gm];
            }
        }
    };
    auto store_chunk = [&](float* buf) {
#pragma unroll
        for (int q = 0; q < 4; q++) {
            float4 v = rv[q];
            if (AGG) {
                float s = __frcp_rn(fmaxf(cf[q], 1.0f));
                v.x *= s; v.y *= s; v.z *= s; v.w *= s;
            }
            float4 c;
            c.x = __uint_as_float(f2tf32(v.x));
            c.y = __uint_as_float(f2tf32(v.y));
            c.z = __uint_as_float(f2tf32(v.z));
            c.w = __uint_as_float(f2tf32(v.w));
            *(float4*)&buf[sm_m[q] * A_STRIDE + (sm_kq[q] << 2)] = c;
        }
    };

    for (int t = blockIdx.x; t < NUM_TILES; t += gridDim.x) {
        const int m_base = t * M_TILE;
        float acc[32];
#pragma unroll
        for (int i = 0; i < 32; i++) acc[i] = 0.f;

        load_chunk(m_base, 0);
        store_chunk(aS0);
        __syncthreads();   // also fences one-time wB stage

#pragma unroll
        for (int chunk = 0; chunk < 2; chunk++) {
            float* cur = chunk ? aS1 : aS0;
            float* nxt = chunk ? aS0 : aS1;

            if (chunk == 0) load_chunk(m_base, 1);   // LDG overlaps MMAs

#pragma unroll
            for (int ka = 0; ka < 8; ka++) {
                const int kag = chunk * 8 + ka;
                float2 bf[4];
#pragma unroll
                for (int j = 0; j < 4; j++) {
                    int nb = warp_n * 32 + j * 8 + grp;
                    bf[j] = *(float2*)&wB[kag * 1024 + nb * 8 + 2 * tig];
                }
                float2 alo[2], ahi[2];
#pragma unroll
                for (int i = 0; i < 2; i++) {
                    int mb = warp_m * 32 + i * 16;
                    alo[i] = *(float2*)&cur[(mb + grp) * A_STRIDE + ka * 8 + 2 * tig];
                    ahi[i] = *(float2*)&cur[(mb + grp + 8) * A_STRIDE + ka * 8 + 2 * tig];
                }
#pragma unroll
                for (int i = 0; i < 2; i++)
#pragma unroll
                    for (int j = 0; j < 4; j++) {
                        float* c = &acc[(i * 4 + j) * 4];
                        asm volatile(
                            "mma.sync.aligned.m16n8k8.row.col.f32.tf32.tf32.f32 "
                            "{%0,%1,%2,%3}, {%4,%5,%6,%7}, {%8,%9}, {%0,%1,%2,%3};"
                            : "+f"(c[0]), "+f"(c[1]), "+f"(c[2]), "+f"(c[3])
                            : "r"(__float_as_uint(alo[i].x)),
                              "r"(__float_as_uint(ahi[i].x)),
                              "r"(__float_as_uint(alo[i].y)),
                              "r"(__float_as_uint(ahi[i].y)),
                              "r"(__float_as_uint(bf[j].x)),
                              "r"(__float_as_uint(bf[j].y)));
                    }
            }

            if (chunk == 0) store_chunk(nxt);
            __syncthreads();
        }

        // ---- Epilogue ----
#pragma unroll
        for (int j = 0; j < 4; j++) {
            int c0 = warp_n * 32 + j * 8 + 2 * tig;
            float b0 = 0.f, b1 = 0.f;
            if (AGG) { b0 = bias[c0]; b1 = bias[c0 + 1]; }
#pragma unroll
            for (int i = 0; i < 2; i++) {
                float* a = &acc[(i * 4 + j) * 4];
                int r0 = m_base + warp_m * 32 + i * 16 + grp;
#pragma unroll
                for (int h = 0; h < 2; h++) {
                    int r = r0 + h * 8;
                    if (r < N_NODES) {
                        float v0 = a[h * 2 + 0];
                        float v1 = a[h * 2 + 1];
                        if (AGG) {
                            float2 pv = *(const float2*)(p_in + (size_t)r * D + c0);
                            v0 += pv.x + b0;
                            v1 += pv.y + b1;
                            if (do_relu) { v0 = fmaxf(v0, 0.f); v1 = fmaxf(v1, 0.f); }
                        }
                        *(float2*)(out + (size_t)r * D + c0) = make_float2(v0, v1);
                    }
                }
            }
        }
    }
}

// ---------------------------------------------------------------------------
// Launcher: fork/join graph — scatter overlaps the x@Wr half-GEMM.
// ---------------------------------------------------------------------------
extern "C" void kernel_launch(void* const* d_in, const int* in_sizes, int n_in,
                              void* d_out, int out_size) {
    const int* edge_index = (const int*)d_in[0];   // int32 (JAX default int)
    const float* node_emb = (const float*)d_in[1];
    const float* w1_l = (const float*)d_in[2];
    const float* b1_l = (const float*)d_in[3];
    const float* w1_r = (const float*)d_in[4];
    const float* w2_l = (const float*)d_in[5];
    const float* b2_l = (const float*)d_in[6];
    const float* w2_r = (const float*)d_in[7];
    float* out = (float*)d_out;

    static bool init_done = false;
    static cudaStream_t s2;
    static cudaEvent_t evFork, evB1, evH1, evB2;
    if (!init_done) {
        cudaFuncSetAttribute(gemm_half<false>,
                             cudaFuncAttributeMaxDynamicSharedMemorySize,
                             GEMM_SMEM_BYTES);
        cudaFuncSetAttribute(gemm_half<true>,
                             cudaFuncAttributeMaxDynamicSharedMemorySize,
                             GEMM_SMEM_BYTES);
        cudaStreamCreateWithFlags(&s2, cudaStreamNonBlocking);
        cudaEventCreateWithFlags(&evFork, cudaEventDisableTiming);
        cudaEventCreateWithFlags(&evB1, cudaEventDisableTiming);
        cudaEventCreateWithFlags(&evH1, cudaEventDisableTiming);
        cudaEventCreateWithFlags(&evB2, cudaEventDisableTiming);
        init_done = true;
    }

    float* aggA_p; cudaGetSymbolAddress((void**)&aggA_p, g_aggA);
    float* aggB_p; cudaGetSymbolAddress((void**)&aggB_p, g_aggB);
    float* cnt_p;  cudaGetSymbolAddress((void**)&cnt_p, g_cnt);
    float* h1_p;   cudaGetSymbolAddress((void**)&h1_p, g_h1);
    float* p_p;    cudaGetSymbolAddress((void**)&p_p, g_p);

    const int agg4 = N_NODES * D / 4;

    // main: zero cnt + aggA (critical path prologue)
    zero_kernel<<<64, 256>>>((float4*)cnt_p, N_NODES / 4);
    zero_kernel<<<2048, 256>>>((float4*)aggA_p, agg4);

    // fork side branch
    cudaEventRecord(evFork, 0);
    cudaStreamWaitEvent(s2, evFork, 0);

    // side: zero aggB (for layer 2) + gemm_x1: P = node_emb @ W1r
    zero_kernel<<<2048, 256, 0, s2>>>((float4*)aggB_p, agg4);
    gemm_half<false><<<112, 512, GEMM_SMEM_BYTES, s2>>>(node_emb, w1_r,
                                                        nullptr, nullptr,
                                                        p_p, 0);
    cudaEventRecord(evB1, s2);

    // main: scatter1 (concurrent with side branch)
    scatter_kernel<<<2048, 256>>>(edge_index, node_emb, aggA_p, 1);

    // join, then gemm_agg1: h1 = relu(aggA/cnt @ W1l + P + b1)
    cudaStreamWaitEvent(0, evB1, 0);
    gemm_half<true><<<148, 512, GEMM_SMEM_BYTES>>>(aggA_p, w1_l, b1_l, p_p,
                                                   h1_p, 1);
    cudaEventRecord(evH1, 0);

    // side: gemm_x2: P = h1 @ W2r   (depends only on h1)
    cudaStreamWaitEvent(s2, evH1, 0);
    gemm_half<false><<<112, 512, GEMM_SMEM_BYTES, s2>>>(h1_p, w2_r,
                                                        nullptr, nullptr,
                                                        p_p, 0);
    cudaEventRecord(evB2, s2);

    // main: scatter2 into aggB (concurrent with gemm_x2)
    scatter_kernel<<<2048, 256>>>(edge_index, h1_p, aggB_p, 0);

    // join, then gemm_agg2: out = aggB/cnt @ W2l + P + b2
    cudaStreamWaitEvent(0, evB2, 0);
    gemm_half<true><<<148, 512, GEMM_SMEM_BYTES>>>(aggB_p, w2_l, b2_l, p_p,
                                                   out, 0);

    (void)in_sizes; (void)n_in; (void)out_size;
}

// round 11
// speedup vs baseline: 1.0239x; 1.0239x over previous
#include <cuda_runtime.h>
#include <cstdint>

#define N_NODES 100000
#define D 128
#define N_EDGES 1000000
#define M_TILE 128
#define NUM_TILES ((N_NODES + M_TILE - 1) / M_TILE)   // 782

// Scratch (no allocation allowed -> __device__ globals)
__device__ alignas(16) float g_agg[(size_t)N_NODES * D];
__device__ alignas(16) float g_h1 [(size_t)N_NODES * D];
__device__ alignas(16) float g_cnt[N_NODES];

// ---------------------------------------------------------------------------
// Zero a float buffer
// ---------------------------------------------------------------------------
__global__ void zero_kernel(float4* p, int count4) {
    int i = blockIdx.x * blockDim.x + threadIdx.x;
    int stride = gridDim.x * blockDim.x;
    float4 z = make_float4(0.f, 0.f, 0.f, 0.f);
    for (; i < count4; i += stride) p[i] = z;
}

// ---------------------------------------------------------------------------
// Scatter: one warp per edge; lane l handles float4 l of the 128-float row.
// Vector reduction (red.global.add.v4.f32). do_count: lane 0 bumps degree.
// ---------------------------------------------------------------------------
__global__ void scatter_kernel(const int* __restrict__ ei,
                               const float* __restrict__ x,
                               int do_count) {
    int gt = blockIdx.x * blockDim.x + threadIdx.x;
    int lane = gt & 31;
    int warp = gt >> 5;
    int nwarps = (gridDim.x * blockDim.x) >> 5;
    for (int e = warp; e < N_EDGES; e += nwarps) {
        int s = ei[e];
        int d = ei[N_EDGES + e];
        s = min(max(s, 0), N_NODES - 1);
        d = min(max(d, 0), N_NODES - 1);
        if (do_count && lane == 0) atomicAdd(&g_cnt[d], 1.0f);
        const float4* srcp = (const float4*)(x + (size_t)s * D);
        float4 v = srcp[lane];
        float* dst = g_agg + (size_t)d * D + lane * 4;
        asm volatile("red.global.add.v4.f32 [%0], {%1,%2,%3,%4};"
                     :: "l"(dst), "f"(v.x), "f"(v.y), "f"(v.z), "f"(v.w)
                     : "memory");
    }
}

// ---------------------------------------------------------------------------
// Fused SAGE GEMM, mma.sync tf32 m16n8k8 — direct-LDG A, no A smem, no
// barriers in the tile loop.
//   out[m,:] = act( (agg[m,:] @ Wl)/cnt[m] + x[m,:] @ Wr + b )
// (row-scaling commutes with the GEMM: applied to the accumulator between
//  the agg half and the x half of the K loop)
// B = W'^T (256x128) staged once per block in k-pair-adjacent layout:
//   wB[ka][n][kk]: word = ka*1024 + n*8 + kk      (CF per half-warp)
// A fragments: lane tig's k-pair (8*ka+2tig, +1) is ADJACENT in global
// memory -> one LDG.64 per row-fragment; warp-wide 8 rows x 32B fully
// sectored. warp_n groups re-read the same rows -> L1 hits (tile 64KB).
// Boundary rows clamped (rows are independent; clamped rows never stored).
// ---------------------------------------------------------------------------
#define B_WORDS (32 * 1024)              // 32 katoms * 128 n * 8 kk = 128 KB
#define GEMM_SMEM_BYTES (B_WORDS * 4)

__device__ __forceinline__ uint32_t f2tf32(float v) {
    uint32_t r;
    asm("cvt.rna.tf32.f32 %0, %1;" : "=r"(r) : "f"(v));
    return r;
}
__device__ __forceinline__ uint32_t f2tf32f(float v) {  // as float bits
    return f2tf32(v);
}

__global__ void __launch_bounds__(512, 1)
sage_gemm_mma(const float* __restrict__ x,
              const float* __restrict__ wl,
              const float* __restrict__ wr,
              const float* __restrict__ bias,
              float* __restrict__ out,
              int do_relu) {
    extern __shared__ float wB[];    // [32 ka][128 n][8 kk]

    const int tid = threadIdx.x;
    const int wid = tid >> 5;
    const int lane = tid & 31;
    const int grp = lane >> 2;    // 0..7
    const int tig = lane & 3;     // 0..3
    const int warp_m = wid & 3;   // m offset = 32*warp_m
    const int warp_n = wid >> 2;  // n offset = 32*warp_n

    // ---- Stage B = W'^T once: wB[ka][n][kk] = tf32(W'[ka*8+kk][n]) ----
    for (int i = tid; i < 8192; i += 512) {
        int n = i & 127;
        int t2 = i >> 7;          // 0..63
        int ka = t2 >> 1;
        int h = t2 & 1;
        int kb = ka * 8 + h * 4;
        float4 c;
        if (kb < 128) {
            c.x = __uint_as_float(f2tf32(wl[(kb + 0) * 128 + n]));
            c.y = __uint_as_float(f2tf32(wl[(kb + 1) * 128 + n]));
            c.z = __uint_as_float(f2tf32(wl[(kb + 2) * 128 + n]));
            c.w = __uint_as_float(f2tf32(wl[(kb + 3) * 128 + n]));
        } else {
            int kr = kb - 128;
            c.x = __uint_as_float(f2tf32(wr[(kr + 0) * 128 + n]));
            c.y = __uint_as_float(f2tf32(wr[(kr + 1) * 128 + n]));
            c.z = __uint_as_float(f2tf32(wr[(kr + 2) * 128 + n]));
            c.w = __uint_as_float(f2tf32(wr[(kr + 3) * 128 + n]));
        }
        *(float4*)&wB[ka * 1024 + n * 8 + h * 4] = c;
    }
    __syncthreads();   // the ONLY barrier

    const int koff = 2 * tig;   // byte-adjacent k pair within each katom

    for (int t = blockIdx.x; t < NUM_TILES; t += gridDim.x) {
        const int m_base = t * M_TILE;

        // row indices (clamped for loads; epilogue guards stores)
        int rlo[2], rhi[2];
        const float *aggLo[2], *aggHi[2], *xLo[2], *xHi[2];
#pragma unroll
        for (int i = 0; i < 2; i++) {
            rlo[i] = m_base + warp_m * 32 + i * 16 + grp;
            rhi[i] = rlo[i] + 8;
            int cl = min(rlo[i], N_NODES - 1);
            int ch = min(rhi[i], N_NODES - 1);
            aggLo[i] = g_agg + (size_t)cl * D + koff;
            aggHi[i] = g_agg + (size_t)ch * D + koff;
            xLo[i]   = x     + (size_t)cl * D + koff;
            xHi[i]   = x     + (size_t)ch * D + koff;
        }

        float acc[32];
#pragma unroll
        for (int i = 0; i < 32; i++) acc[i] = 0.f;

        // ---- agg half: katoms 0..15 (global k 0..127 of agg) ----
#pragma unroll
        for (int ka = 0; ka < 16; ka++) {
            float2 bf[4];
#pragma unroll
            for (int j = 0; j < 4; j++) {
                int nb = warp_n * 32 + j * 8 + grp;
                bf[j] = *(float2*)&wB[ka * 1024 + nb * 8 + 2 * tig];
            }
            uint32_t a0[2], a1[2], a2[2], a3[2];
#pragma unroll
            for (int i = 0; i < 2; i++) {
                float2 lo = *(const float2*)(aggLo[i] + ka * 8);
                float2 hi = *(const float2*)(aggHi[i] + ka * 8);
                a0[i] = f2tf32f(lo.x); a2[i] = f2tf32f(lo.y);
                a1[i] = f2tf32f(hi.x); a3[i] = f2tf32f(hi.y);
            }
#pragma unroll
            for (int i = 0; i < 2; i++)
#pragma unroll
                for (int j = 0; j < 4; j++) {
                    float* c = &acc[(i * 4 + j) * 4];
                    asm volatile(
                        "mma.sync.aligned.m16n8k8.row.col.f32.tf32.tf32.f32 "
                        "{%0,%1,%2,%3}, {%4,%5,%6,%7}, {%8,%9}, {%0,%1,%2,%3};"
                        : "+f"(c[0]), "+f"(c[1]), "+f"(c[2]), "+f"(c[3])
                        : "r"(a0[i]), "r"(a1[i]), "r"(a2[i]), "r"(a3[i]),
                          "r"(__float_as_uint(bf[j].x)),
                          "r"(__float_as_uint(bf[j].y)));
                }
        }

        // ---- scale agg contribution by 1/cnt (per accumulator row) ----
        {
            float invLo[2], invHi[2];
#pragma unroll
            for (int i = 0; i < 2; i++) {
                invLo[i] = __frcp_rn(fmaxf(g_cnt[min(rlo[i], N_NODES - 1)], 1.0f));
                invHi[i] = __frcp_rn(fmaxf(g_cnt[min(rhi[i], N_NODES - 1)], 1.0f));
            }
#pragma unroll
            for (int i = 0; i < 2; i++)
#pragma unroll
                for (int j = 0; j < 4; j++) {
                    float* c = &acc[(i * 4 + j) * 4];
                    c[0] *= invLo[i]; c[1] *= invLo[i];
                    c[2] *= invHi[i]; c[3] *= invHi[i];
                }
        }

        // ---- x half: katoms 16..31 (global k 0..127 of x) ----
#pragma unroll
        for (int ka = 0; ka < 16; ka++) {
            const int kag = 16 + ka;
            float2 bf[4];
#pragma unroll
            for (int j = 0; j < 4; j++) {
                int nb = warp_n * 32 + j * 8 + grp;
                bf[j] = *(float2*)&wB[kag * 1024 + nb * 8 + 2 * tig];
            }
            uint32_t a0[2], a1[2], a2[2], a3[2];
#pragma unroll
            for (int i = 0; i < 2; i++) {
                float2 lo = *(const float2*)(xLo[i] + ka * 8);
                float2 hi = *(const float2*)(xHi[i] + ka * 8);
                a0[i] = f2tf32f(lo.x); a2[i] = f2tf32f(lo.y);
                a1[i] = f2tf32f(hi.x); a3[i] = f2tf32f(hi.y);
            }
#pragma unroll
            for (int i = 0; i < 2; i++)
#pragma unroll
                for (int j = 0; j < 4; j++) {
                    float* c = &acc[(i * 4 + j) * 4];
                    asm volatile(
                        "mma.sync.aligned.m16n8k8.row.col.f32.tf32.tf32.f32 "
                        "{%0,%1,%2,%3}, {%4,%5,%6,%7}, {%8,%9}, {%0,%1,%2,%3};"
                        : "+f"(c[0]), "+f"(c[1]), "+f"(c[2]), "+f"(c[3])
                        : "r"(a0[i]), "r"(a1[i]), "r"(a2[i]), "r"(a3[i]),
                          "r"(__float_as_uint(bf[j].x)),
                          "r"(__float_as_uint(bf[j].y)));
                }
        }

        // ---- Epilogue: bias (+ReLU), store float2 per c-pair ----
#pragma unroll
        for (int j = 0; j < 4; j++) {
            int c0 = warp_n * 32 + j * 8 + 2 * tig;
            float b0 = bias[c0], b1 = bias[c0 + 1];
#pragma unroll
            for (int i = 0; i < 2; i++) {
                float* a = &acc[(i * 4 + j) * 4];
#pragma unroll
                for (int h = 0; h < 2; h++) {
                    int r = (h == 0) ? rlo[i] : rhi[i];
                    if (r < N_NODES) {
                        float v0 = a[h * 2 + 0] + b0;
                        float v1 = a[h * 2 + 1] + b1;
                        if (do_relu) { v0 = fmaxf(v0, 0.f); v1 = fmaxf(v1, 0.f); }
                        *(float2*)(out + (size_t)r * D + c0) = make_float2(v0, v1);
                    }
                }
            }
        }
    }
}

// ---------------------------------------------------------------------------
// Launcher (single stream, round-8 structure)
// ---------------------------------------------------------------------------
extern "C" void kernel_launch(void* const* d_in, const int* in_sizes, int n_in,
                              void* d_out, int out_size) {
    const int* edge_index = (const int*)d_in[0];   // int32 (JAX default int)
    const float* node_emb = (const float*)d_in[1];
    const float* w1_l = (const float*)d_in[2];
    const float* b1_l = (const float*)d_in[3];
    const float* w1_r = (const float*)d_in[4];
    const float* w2_l = (const float*)d_in[5];
    const float* b2_l = (const float*)d_in[6];
    const float* w2_r = (const float*)d_in[7];
    float* out = (float*)d_out;

    static bool attr_set = false;
    if (!attr_set) {
        cudaFuncSetAttribute(sage_gemm_mma,
                             cudaFuncAttributeMaxDynamicSharedMemorySize,
                             GEMM_SMEM_BYTES);
        attr_set = true;
    }

    float* agg_p;  cudaGetSymbolAddress((void**)&agg_p, g_agg);
    float* cnt_p;  cudaGetSymbolAddress((void**)&cnt_p, g_cnt);
    float* h1_p;   cudaGetSymbolAddress((void**)&h1_p, g_h1);

    const int agg4 = N_NODES * D / 4;

    // zero counts + layer-1 accumulator
    zero_kernel<<<64, 256>>>((float4*)cnt_p, N_NODES / 4);
    zero_kernel<<<2048, 256>>>((float4*)agg_p, agg4);

    // --- layer 1 ---
    scatter_kernel<<<2048, 256>>>(edge_index, node_emb, 1);
    sage_gemm_mma<<<148, 512, GEMM_SMEM_BYTES>>>(node_emb, w1_l, w1_r, b1_l,
                                                 h1_p, 1);

    // --- layer 2 ---
    zero_kernel<<<2048, 256>>>((float4*)agg_p, agg4);
    scatter_kernel<<<2048, 256>>>(edge_index, h1_p, 0);
    sage_gemm_mma<<<148, 512, GEMM_SMEM_BYTES>>>(h1_p, w2_l, w2_r, b2_l,
                                                 out, 0);

    (void)in_sizes; (void)n_in; (void)out_size;
}

// round 13
// speedup vs baseline: 1.0549x; 1.0303x over previous
#include <cuda_runtime.h>
#include <cstdint>

#define N_NODES 100000
#define D 128
#define N_EDGES 1000000
#define M_TILE 128
#define NUM_TILES ((N_NODES + M_TILE - 1) / M_TILE)   // 782

// Scratch (no allocation allowed -> __device__ globals)
__device__ alignas(16) float g_agg[(size_t)N_NODES * D];
__device__ alignas(16) float g_h1 [(size_t)N_NODES * D];
__device__ alignas(16) float g_cnt[N_NODES];

// ---------------------------------------------------------------------------
// Zero a float buffer
// ---------------------------------------------------------------------------
__global__ void zero_kernel(float4* p, int count4) {
    int i = blockIdx.x * blockDim.x + threadIdx.x;
    int stride = gridDim.x * blockDim.x;
    float4 z = make_float4(0.f, 0.f, 0.f, 0.f);
    for (; i < count4; i += stride) p[i] = z;
}

// ---------------------------------------------------------------------------
// Scatter: one warp per edge; lane l handles float4 l of the 128-float row.
// Vector reduction (red.global.add.v4.f32). do_count: lane 0 bumps degree.
// ---------------------------------------------------------------------------
__global__ void scatter_kernel(const int* __restrict__ ei,
                               const float* __restrict__ x,
                               int do_count) {
    int gt = blockIdx.x * blockDim.x + threadIdx.x;
    int lane = gt & 31;
    int warp = gt >> 5;
    int nwarps = (gridDim.x * blockDim.x) >> 5;
    for (int e = warp; e < N_EDGES; e += nwarps) {
        int s = ei[e];
        int d = ei[N_EDGES + e];
        s = min(max(s, 0), N_NODES - 1);
        d = min(max(d, 0), N_NODES - 1);
        if (do_count && lane == 0) atomicAdd(&g_cnt[d], 1.0f);
        const float4* srcp = (const float4*)(x + (size_t)s * D);
        float4 v = srcp[lane];
        float* dst = g_agg + (size_t)d * D + lane * 4;
        asm volatile("red.global.add.v4.f32 [%0], {%1,%2,%3,%4};"
                     :: "l"(dst), "f"(v.x), "f"(v.y), "f"(v.z), "f"(v.w)
                     : "memory");
    }
}

// ---------------------------------------------------------------------------
// Fused SAGE GEMM, mma.sync tf32 m16n8k8 — N-split for 2 CTAs/SM.
//   out[m,n0:n0+64] = act( (agg[m]@Wl)/cnt[m] + x[m]@Wr + b )[n0:n0+64]
// Each block owns a 64-wide n-half (blockIdx.x&1); B smem 64KB + A 36KB =
// 100KB/CTA -> 2 CTAs co-resident (occ 50%); co-resident CTA hides the
// other's staging/barrier bubbles (no double-buffer / prefetch needed,
// which fits the 64-reg budget of __launch_bounds__(512,2)).
// Mean division commuted onto the accumulator after the agg half.
//   wB[ka][nn][kk]: word = ka*512 + nn*8 + kk     (CF per half-warp)
//   aS[m][kq*4]   : word = m*72 + kq*4            (stride 72 ≡ 8 mod 32, CF)
// ---------------------------------------------------------------------------
#define B_WORDS (32 * 512)               // 32 katoms * 64 n * 8 kk = 64 KB
#define A_STRIDE 72
#define A_WORDS (128 * A_STRIDE)         // 36 KB
#define GEMM_SMEM_BYTES ((B_WORDS + A_WORDS) * 4)   // 102400

__device__ __forceinline__ uint32_t f2tf32(float v) {
    uint32_t r;
    asm("cvt.rna.tf32.f32 %0, %1;" : "=r"(r) : "f"(v));
    return r;
}

__global__ void __launch_bounds__(512, 2)
sage_gemm_mma(const float* __restrict__ x,
              const float* __restrict__ wl,
              const float* __restrict__ wr,
              const float* __restrict__ bias,
              float* __restrict__ out,
              int do_relu) {
    extern __shared__ float sm[];
    float* wB = sm;               // [32 ka][64 nn][8 kk]
    float* aS = sm + B_WORDS;     // [128 m][A_STRIDE]

    const int tid = threadIdx.x;
    const int wid = tid >> 5;
    const int lane = tid & 31;
    const int grp = lane >> 2;    // 0..7
    const int tig = lane & 3;     // 0..3
    const int warp_m = wid & 3;   // m offset = 32*warp_m
    const int warp_n = wid >> 2;  // n offset (local) = 16*warp_n

    const int nh = blockIdx.x & 1;
    const int n0 = nh * 64;       // global n offset of this block's half

    // ---- Stage B-half once: wB[ka][nn][kk] = tf32(W'[ka*8+kk][n0+nn]) ----
    for (int i = tid; i < 4096; i += 512) {
        int nn = i & 63;
        int t2 = i >> 6;          // 0..63
        int ka = t2 >> 1;
        int h = t2 & 1;
        int kb = ka * 8 + h * 4;
        int n = n0 + nn;
        float4 c;
        if (kb < 128) {
            c.x = __uint_as_float(f2tf32(wl[(kb + 0) * 128 + n]));
            c.y = __uint_as_float(f2tf32(wl[(kb + 1) * 128 + n]));
            c.z = __uint_as_float(f2tf32(wl[(kb + 2) * 128 + n]));
            c.w = __uint_as_float(f2tf32(wl[(kb + 3) * 128 + n]));
        } else {
            int kr = kb - 128;
            c.x = __uint_as_float(f2tf32(wr[(kr + 0) * 128 + n]));
            c.y = __uint_as_float(f2tf32(wr[(kr + 1) * 128 + n]));
            c.z = __uint_as_float(f2tf32(wr[(kr + 2) * 128 + n]));
            c.w = __uint_as_float(f2tf32(wr[(kr + 3) * 128 + n]));
        }
        *(float4*)&wB[ka * 512 + nn * 8 + h * 4] = c;
    }

    const int mt_stride = gridDim.x >> 1;   // 148

    for (int t = (blockIdx.x >> 1); t < NUM_TILES; t += mt_stride) {
        const int m_base = t * M_TILE;

        int rlo[2], rhi[2];
#pragma unroll
        for (int i = 0; i < 2; i++) {
            rlo[i] = m_base + warp_m * 32 + i * 16 + grp;
            rhi[i] = rlo[i] + 8;
        }

        float acc[16];
#pragma unroll
        for (int i = 0; i < 16; i++) acc[i] = 0.f;

#pragma unroll
        for (int chunk = 0; chunk < 4; chunk++) {
            __syncthreads();   // previous chunk's consumers done (also wB fence)
            // ---- Stage A chunk [128 m][64 k] (chunks 0,1: agg; 2,3: x) ----
            for (int q = 0; q < 4; q++) {
                int i = tid + q * 512;
                int m = i >> 4;
                int kq = i & 15;
                int gm = m_base + m;
                float4 v = make_float4(0.f, 0.f, 0.f, 0.f);
                if (gm < N_NODES) {
                    int kg = chunk * 64 + (kq << 2);
                    if (kg < 128)
                        v = *(const float4*)(g_agg + (size_t)gm * D + kg);
                    else
                        v = *(const float4*)(x + (size_t)gm * D + (kg - 128));
                }
                float4 c;
                c.x = __uint_as_float(f2tf32(v.x));
                c.y = __uint_as_float(f2tf32(v.y));
                c.z = __uint_as_float(f2tf32(v.z));
                c.w = __uint_as_float(f2tf32(v.w));
                *(float4*)&aS[m * A_STRIDE + (kq << 2)] = c;
            }
            __syncthreads();

            // ---- Compute: 8 katoms of K=8 ----
#pragma unroll
            for (int ka = 0; ka < 8; ka++) {
                const int kag = chunk * 8 + ka;
                float2 bf[2];
#pragma unroll
                for (int j = 0; j < 2; j++) {
                    int nb = warp_n * 16 + j * 8 + grp;
                    bf[j] = *(float2*)&wB[kag * 512 + nb * 8 + 2 * tig];
                }
                float2 alo[2], ahi[2];
#pragma unroll
                for (int i = 0; i < 2; i++) {
                    int mb = warp_m * 32 + i * 16;
                    alo[i] = *(float2*)&aS[(mb + grp) * A_STRIDE + ka * 8 + 2 * tig];
                    ahi[i] = *(float2*)&aS[(mb + grp + 8) * A_STRIDE + ka * 8 + 2 * tig];
                }
#pragma unroll
                for (int i = 0; i < 2; i++)
#pragma unroll
                    for (int j = 0; j < 2; j++) {
                        float* c = &acc[(i * 2 + j) * 4];
                        asm volatile(
                            "mma.sync.aligned.m16n8k8.row.col.f32.tf32.tf32.f32 "
                            "{%0,%1,%2,%3}, {%4,%5,%6,%7}, {%8,%9}, {%0,%1,%2,%3};"
                            : "+f"(c[0]), "+f"(c[1]), "+f"(c[2]), "+f"(c[3])
                            : "r"(__float_as_uint(alo[i].x)),
                              "r"(__float_as_uint(ahi[i].x)),
                              "r"(__float_as_uint(alo[i].y)),
                              "r"(__float_as_uint(ahi[i].y)),
                              "r"(__float_as_uint(bf[j].x)),
                              "r"(__float_as_uint(bf[j].y)));
                    }
            }

            // ---- after agg half (chunks 0,1): scale acc by 1/cnt ----
            if (chunk == 1) {
#pragma unroll
                for (int i = 0; i < 2; i++) {
                    float il = __frcp_rn(fmaxf(g_cnt[min(rlo[i], N_NODES - 1)], 1.0f));
                    float ih = __frcp_rn(fmaxf(g_cnt[min(rhi[i], N_NODES - 1)], 1.0f));
#pragma unroll
                    for (int j = 0; j < 2; j++) {
                        float* c = &acc[(i * 2 + j) * 4];
                        c[0] *= il; c[1] *= il;
                        c[2] *= ih; c[3] *= ih;
                    }
                }
            }
        }

        // ---- Epilogue: bias (+ReLU), store float2 per c-pair ----
#pragma unroll
        for (int j = 0; j < 2; j++) {
            int c0 = n0 + warp_n * 16 + j * 8 + 2 * tig;
            float b0 = bias[c0], b1 = bias[c0 + 1];
#pragma unroll
            for (int i = 0; i < 2; i++) {
                float* a = &acc[(i * 2 + j) * 4];
#pragma unroll
                for (int h = 0; h < 2; h++) {
                    int r = (h == 0) ? rlo[i] : rhi[i];
                    if (r < N_NODES) {
                        float v0 = a[h * 2 + 0] + b0;
                        float v1 = a[h * 2 + 1] + b1;
                        if (do_relu) { v0 = fmaxf(v0, 0.f); v1 = fmaxf(v1, 0.f); }
                        *(float2*)(out + (size_t)r * D + c0) = make_float2(v0, v1);
                    }
                }
            }
        }
    }
}

// ---------------------------------------------------------------------------
// Launcher (single stream)
// ---------------------------------------------------------------------------
extern "C" void kernel_launch(void* const* d_in, const int* in_sizes, int n_in,
                              void* d_out, int out_size) {
    const int* edge_index = (const int*)d_in[0];   // int32 (JAX default int)
    const float* node_emb = (const float*)d_in[1];
    const float* w1_l = (const float*)d_in[2];
    const float* b1_l = (const float*)d_in[3];
    const float* w1_r = (const float*)d_in[4];
    const float* w2_l = (const float*)d_in[5];
    const float* b2_l = (const float*)d_in[6];
    const float* w2_r = (const float*)d_in[7];
    float* out = (float*)d_out;

    static bool attr_set = false;
    if (!attr_set) {
        cudaFuncSetAttribute(sage_gemm_mma,
                             cudaFuncAttributeMaxDynamicSharedMemorySize,
                             GEMM_SMEM_BYTES);
        attr_set = true;
    }

    float* agg_p;  cudaGetSymbolAddress((void**)&agg_p, g_agg);
    float* cnt_p;  cudaGetSymbolAddress((void**)&cnt_p, g_cnt);
    float* h1_p;   cudaGetSymbolAddress((void**)&h1_p, g_h1);

    const int agg4 = N_NODES * D / 4;

    // zero counts + layer-1 accumulator
    zero_kernel<<<64, 256>>>((float4*)cnt_p, N_NODES / 4);
    zero_kernel<<<2048, 256>>>((float4*)agg_p, agg4);

    // --- layer 1 ---
    scatter_kernel<<<2048, 256>>>(edge_index, node_emb, 1);
    sage_gemm_mma<<<296, 512, GEMM_SMEM_BYTES>>>(node_emb, w1_l, w1_r, b1_l,
                                                 h1_p, 1);

    // --- layer 2 ---
    zero_kernel<<<2048, 256>>>((float4*)agg_p, agg4);
    scatter_kernel<<<2048, 256>>>(edge_index, h1_p, 0);
    sage_gemm_mma<<<296, 512, GEMM_SMEM_BYTES>>>(h1_p, w2_l, w2_r, b2_l,
                                                 out, 0);

    (void)in_sizes; (void)n_in; (void)out_size;
}